// round 10
// baseline (speedup 1.0000x reference)
#include <cuda_runtime.h>
#include <cuda_bf16.h>
#include <cuda_fp16.h>
#include <math.h>
#include <stdint.h>

// ---------------- problem constants ----------------
#define H_DIM 4096
#define NH 32
#define NKV 2
#define HD 128
#define ROT 64
#define BB 2
#define SS 2048
#define QKV_DIM ((NH + 2*NKV)*HD)   // 4608
#define TOK (BB*SS)                 // 4096

// scratch (allocation-free rule: device globals)
__device__ __half g_W1[(size_t)QKV_DIM * H_DIM];     // Wqkv^T fp16 [N][K]
__device__ __half g_W2[(size_t)H_DIM * H_DIM];       // Wo^T fp16 [N][K]
__device__ __half g_A_h[(size_t)TOK * H_DIM];
__device__ __half g_A_l[(size_t)TOK * H_DIM];
__device__ __half g_Qh[(size_t)TOK * NH * HD];
__device__ __half g_Ql[(size_t)TOK * NH * HD];
__device__ __half g_K1[(size_t)TOK * NKV * HD];
__device__ __half g_Vt[(size_t)TOK * NKV * HD];
__device__ float2 g_rope[SS * (ROT/2)];

// ---------------- PTX helpers ----------------
__device__ __forceinline__ uint32_t smem_u32(const void* p) {
    uint32_t a;
    asm("{ .reg .u64 t; cvta.to.shared.u64 t, %1; cvt.u32.u64 %0, t; }"
        : "=r"(a) : "l"(p));
    return a;
}
__device__ __forceinline__ void ldsm4(uint32_t* r, uint32_t addr) {
    asm volatile("ldmatrix.sync.aligned.m8n8.x4.shared.b16 {%0,%1,%2,%3}, [%4];"
                 : "=r"(r[0]), "=r"(r[1]), "=r"(r[2]), "=r"(r[3]) : "r"(addr));
}
__device__ __forceinline__ void mma_f16(float* d, const uint32_t* a,
                                        uint32_t b0, uint32_t b1) {
    asm volatile("mma.sync.aligned.m16n8k16.row.col.f32.f16.f16.f32 "
                 "{%0,%1,%2,%3}, {%4,%5,%6,%7}, {%8,%9}, {%0,%1,%2,%3};"
                 : "+f"(d[0]), "+f"(d[1]), "+f"(d[2]), "+f"(d[3])
                 : "r"(a[0]), "r"(a[1]), "r"(a[2]), "r"(a[3]), "r"(b0), "r"(b1));
}
__device__ __forceinline__ uint32_t pack_h2(float lo, float hi) {
    __half2 t = __floats2half2_rn(lo, hi);
    return *(uint32_t*)&t;
}
__device__ __forceinline__ float h_hi(float x) {
    return __half2float(__float2half_rn(x));
}
#define CP_ASYNC16(dst, src) \
    asm volatile("cp.async.cg.shared.global [%0], [%1], 16;" :: "r"(dst), "l"(src))
#define CP_COMMIT() asm volatile("cp.async.commit_group;" ::: "memory")
#define CP_WAIT1() asm volatile("cp.async.wait_group 1;" ::: "memory")
#define CP_WAIT0() asm volatile("cp.async.wait_group 0;" ::: "memory")

// ---------------- conversion kernels ----------------
__global__ void split_f16_kernel(const float4* __restrict__ x,
                                 __half2* __restrict__ h,
                                 __half2* __restrict__ l, int n4)
{
    int i = blockIdx.x * blockDim.x + threadIdx.x;
    if (i >= n4) return;
    float4 v = x[i];
    float h0 = h_hi(v.x), h1 = h_hi(v.y), h2 = h_hi(v.z), h3 = h_hi(v.w);
    h[2*i]   = __floats2half2_rn(h0, h1);
    h[2*i+1] = __floats2half2_rn(h2, h3);
    l[2*i]   = __floats2half2_rn(v.x - h0, v.y - h1);
    l[2*i+1] = __floats2half2_rn(v.z - h2, v.w - h3);
}

__global__ void transpose_f16_kernel(const float* __restrict__ W,
                                     __half* __restrict__ T, int K, int N)
{
    __shared__ float t[32][33];
    int n0 = blockIdx.x * 32, k0 = blockIdx.y * 32;
    int tx = threadIdx.x & 31, g = threadIdx.x >> 5;
    #pragma unroll
    for (int j = 0; j < 4; j++) {
        int ky = g * 4 + j;
        t[ky][tx] = W[(size_t)(k0 + ky) * N + n0 + tx];
    }
    __syncthreads();
    #pragma unroll
    for (int j = 0; j < 4; j++) {
        int ny = g * 4 + j;
        T[(size_t)(n0 + ny) * K + k0 + tx] = __float2half_rn(t[tx][ny]);
    }
}

__global__ void rope_table_kernel(float2* __restrict__ tab)
{
    int idx = blockIdx.x * blockDim.x + threadIdx.x;
    if (idx >= SS * (ROT/2)) return;
    int s = idx >> 5, i = idx & 31;
    float inv  = 1.0f / powf(10000.0f, (float)(2 * i) / (float)ROT);
    float freq = (float)s * inv;
    double fd = (double)freq;
    tab[idx] = make_float2((float)cos(fd), (float)sin(fd));
}

// ---------------- fp16 2-term HMMA GEMM, 128x256 CTA, 512 thr, 3-stage ------
#define BMg 128
#define BNg 256
#define BKg 32
#define ROWB 80
#define TSZ  (128*ROWB)          // 10240 (per A tensor)
#define TSZB (256*ROWB)          // 20480 (W)
#define STGSZ (2*TSZ + TSZB)     // 40960
#define GSMEM (3*STGSZ)          // 122880

template<int MODE>
__global__ __launch_bounds__(512, 1) void gemm_f16_kernel(
    const __half* __restrict__ Ah, const __half* __restrict__ Al,
    const __half* __restrict__ Bw,
    const float* __restrict__ bias, float* __restrict__ C,
    int M, int N, int K,
    const float2* __restrict__ tab,
    __half* __restrict__ Qh, __half* __restrict__ Ql,
    __half* __restrict__ Kq, __half* __restrict__ Vt)
{
    extern __shared__ char smem[];
    const uint32_t sb = smem_u32(smem);
    const int tid = threadIdx.x;
    const int wid = tid >> 5;
    const int lane = tid & 31;
    const int m0 = blockIdx.y * BMg;
    const int n0 = blockIdx.x * BNg;
    const int NC = K / BKg;

    const int wm = (wid >> 3) * 64;   // 2 warp-rows
    const int wn = (wid & 7) * 32;    // 8 warp-cols

    const int a_row = (lane & 7) + ((lane >> 3) & 1) * 8;
    const int a_kh  = (lane >> 4) * 8;
    const int b_row = (lane & 7) + ((lane >> 4) & 1) * 8;
    const int b_kh  = ((lane >> 3) & 1) * 8;

    float acc[4][4][4];
    #pragma unroll
    for (int i = 0; i < 4; i++)
        #pragma unroll
        for (int j = 0; j < 4; j++)
            #pragma unroll
            for (int q = 0; q < 4; q++) acc[i][j][q] = 0.f;

    const int lr = tid >> 2;          // 0..127
    const int lc = tid & 3;
    auto issue_loads = [&](int c, int buf) {
        const int k0 = c * BKg;
        const uint32_t sbuf = sb + buf * STGSZ;
        // A hi/lo: 128 rows each, one 16B unit per thread per tensor
        CP_ASYNC16(sbuf + lr * ROWB + lc * 16,
                   Ah + (size_t)(m0 + lr) * K + k0 + lc * 8);
        CP_ASYNC16(sbuf + TSZ + lr * ROWB + lc * 16,
                   Al + (size_t)(m0 + lr) * K + k0 + lc * 8);
        // W: 256 rows
        #pragma unroll
        for (int i = 0; i < 2; i++) {
            int r = i * 128 + lr;
            CP_ASYNC16(sbuf + 2 * TSZ + r * ROWB + lc * 16,
                       Bw + (size_t)(n0 + r) * K + k0 + lc * 8);
        }
        CP_COMMIT();
    };

    auto compute = [&](int buf) {
        const uint32_t sbuf = sb + buf * STGSZ;
        #pragma unroll
        for (int ks = 0; ks < 2; ks++) {
            uint32_t br[2][4];
            #pragma unroll
            for (int g = 0; g < 2; g++) {
                uint32_t addr = sbuf + 2 * TSZ +
                    (wn + g * 16 + b_row) * ROWB + (ks * 16 + b_kh) * 2;
                ldsm4(br[g], addr);
            }
            #pragma unroll
            for (int mt = 0; mt < 4; mt++) {
                uint32_t ah[4], al[4];
                uint32_t addrA = sbuf +
                    (wm + mt * 16 + a_row) * ROWB + (ks * 16 + a_kh) * 2;
                ldsm4(ah, addrA);
                ldsm4(al, addrA + TSZ);
                #pragma unroll
                for (int g = 0; g < 2; g++) {
                    #pragma unroll
                    for (int h8 = 0; h8 < 2; h8++) {
                        const int nt = g * 2 + h8;
                        mma_f16(acc[mt][nt], ah, br[g][h8*2], br[g][h8*2+1]);
                        mma_f16(acc[mt][nt], al, br[g][h8*2], br[g][h8*2+1]);
                    }
                }
            }
        }
    };

    // 3-stage pipeline, one barrier per chunk
    issue_loads(0, 0);
    issue_loads(1, 1);
    for (int c = 0; c < NC; ++c) {
        if (c + 1 < NC) CP_WAIT1();
        else            CP_WAIT0();
        __syncthreads();
        if (c + 2 < NC) issue_loads(c + 2, (c + 2) % 3);
        compute(c % 3);
    }

    if (MODE == 0) {
        #pragma unroll
        for (int mt = 0; mt < 4; mt++) {
            const int m = m0 + wm + mt * 16 + (lane >> 2);
            #pragma unroll
            for (int nt = 0; nt < 4; nt++) {
                const int n = n0 + wn + nt * 8 + (lane & 3) * 2;
                float b0 = 0.f, b1 = 0.f;
                if (bias) { b0 = bias[n]; b1 = bias[n + 1]; }
                float2 v0, v1;
                v0.x = acc[mt][nt][0] + b0; v0.y = acc[mt][nt][1] + b1;
                v1.x = acc[mt][nt][2] + b0; v1.y = acc[mt][nt][3] + b1;
                *(float2*)&C[(size_t)m * N + n] = v0;
                *(float2*)&C[(size_t)(m + 8) * N + n] = v1;
            }
        }
    } else {
        const int slot = (n0 + wn) >> 7;     // constant per warp (wn mult of 32, slot 128-aligned per 4 warps)
        const int kvv = slot - NH;
        const int kvslot = slot - NH - NKV;
        #pragma unroll
        for (int mt = 0; mt < 4; mt++) {
            const int mrow = m0 + wm + mt * 16 + (lane >> 2);
            const int s0 = mrow & (SS - 1), bb0 = mrow >> 11;
            const int s1 = (mrow + 8) & (SS - 1), bb1 = (mrow + 8) >> 11;
            #pragma unroll
            for (int nt = 0; nt < 4; nt++) {
                const int n = n0 + wn + nt * 8 + (lane & 3) * 2;
                const int d = n & 127;
                float v0 = acc[mt][nt][0] + bias[n];
                float v1 = acc[mt][nt][1] + bias[n + 1];
                float v2 = acc[mt][nt][2] + bias[n];
                float v3 = acc[mt][nt][3] + bias[n + 1];
                if (slot < NH + NKV && d < ROT) {
                    float2 c0 = tab[s0 * (ROT/2) + (d >> 1)];
                    float o0 = v0 * c0.x - v1 * c0.y;
                    float o1 = v1 * c0.x + v0 * c0.y;
                    v0 = o0; v1 = o1;
                    float2 c1 = tab[s1 * (ROT/2) + (d >> 1)];
                    float o2 = v2 * c1.x - v3 * c1.y;
                    float o3 = v3 * c1.x + v2 * c1.y;
                    v2 = o2; v3 = o3;
                }
                if (slot < NH) {
                    float h0 = h_hi(v0), h1 = h_hi(v1);
                    float h2 = h_hi(v2), h3 = h_hi(v3);
                    size_t base0 = ((size_t)(bb0 * NH + slot) * SS + s0) * HD + d;
                    size_t base1 = ((size_t)(bb1 * NH + slot) * SS + s1) * HD + d;
                    *(uint32_t*)&Qh[base0] = pack_h2(h0, h1);
                    *(uint32_t*)&Ql[base0] = pack_h2(v0 - h0, v1 - h1);
                    *(uint32_t*)&Qh[base1] = pack_h2(h2, h3);
                    *(uint32_t*)&Ql[base1] = pack_h2(v2 - h2, v3 - h3);
                } else if (slot < NH + NKV) {
                    size_t base0 = ((size_t)(bb0 * NKV + kvv) * SS + s0) * HD + d;
                    size_t base1 = ((size_t)(bb1 * NKV + kvv) * SS + s1) * HD + d;
                    *(uint32_t*)&Kq[base0] = pack_h2(v0, v1);
                    *(uint32_t*)&Kq[base1] = pack_h2(v2, v3);
                } else {
                    size_t vb0 = ((size_t)(bb0 * NKV + kvslot) * HD + d) * SS + s0;
                    size_t vb1 = ((size_t)(bb1 * NKV + kvslot) * HD + d) * SS + s1;
                    Vt[vb0]      = __float2half_rn(v0);
                    Vt[vb0 + SS] = __float2half_rn(v1);
                    Vt[vb1]      = __float2half_rn(v2);
                    Vt[vb1 + SS] = __float2half_rn(v3);
                }
            }
        }
    }
}

// ---------------- HMMA flash attention (AK=128; 2-term S, 1-term PV) ---------
#define AQ 128
#define AK 128
#define QR 272                 // 128 half + 16B pad
#define SQH (AQ*QR)            // 34816
#define SKH (AK*QR)            // 34816 (K stage: 128 rows)
#define SVH (HD*QR)            // 34816 (Vt stage: 128 d-rows x 128 cols + pad)
#define STG (SKH + SVH)        // 69632
#define ASMEM (2*SQH + 2*STG)  // 208896

__global__ __launch_bounds__(256, 1) void attn_kernel(
    const __half* __restrict__ Qh_g, const __half* __restrict__ Ql_g,
    const __half* __restrict__ K_g, const __half* __restrict__ Vt_g,
    __half* __restrict__ Oh_g, __half* __restrict__ Ol_g)
{
    extern __shared__ char smem[];
    const uint32_t sb = smem_u32(smem);
    const int tid = threadIdx.x;
    const int wid = tid >> 5;
    const int lane = tid & 31;
    const int qt = gridDim.x - 1 - blockIdx.x;   // LPT: long CTAs first
    const int h  = blockIdx.y;
    const int b  = blockIdx.z;
    const int kvh = h / (NH / NKV);
    const int qbase = qt * AQ;
    const int ktmax = qt;

    const size_t qoff = ((size_t)(b * NH + h) * SS + qbase) * HD;
    const size_t koff = ((size_t)(b * NKV + kvh) * SS) * HD;
    const size_t voff = ((size_t)(b * NKV + kvh) * HD) * SS;

    const int a_row = (lane & 7) + ((lane >> 3) & 1) * 8;
    const int a_kh  = (lane >> 4) * 8;
    const int b_row = (lane & 7) + ((lane >> 4) & 1) * 8;
    const int b_kh  = ((lane >> 3) & 1) * 8;

    // Q hi/lo -> smem (plain loads)
    #pragma unroll
    for (int i = 0; i < 8; i++) {
        int flat = i * 256 + tid;
        int r = flat >> 4, u = flat & 15;
        *(uint4*)(smem + r * QR + u * 16) =
            *(const uint4*)(Qh_g + qoff + (size_t)r * HD + u * 8);
        *(uint4*)(smem + SQH + r * QR + u * 16) =
            *(const uint4*)(Ql_g + qoff + (size_t)r * HD + u * 8);
    }

    auto issue_kv = [&](int kt, int buf) {
        const int kbase = kt * AK;
        const uint32_t st = sb + 2 * SQH + buf * STG;
        #pragma unroll
        for (int i = 0; i < 8; i++) {     // K: 128 rows x 16 units
            int flat = i * 256 + tid;
            int r = flat >> 4, u = flat & 15;
            CP_ASYNC16(st + r * QR + u * 16,
                       K_g + koff + (size_t)(kbase + r) * HD + u * 8);
        }
        #pragma unroll
        for (int i = 0; i < 8; i++) {     // Vt: 128 d-rows x 16 units
            int flat = i * 256 + tid;
            int r = flat >> 4, u = flat & 15;
            CP_ASYNC16(st + SKH + r * QR + u * 16,
                       Vt_g + voff + (size_t)r * SS + kbase + u * 8);
        }
        CP_COMMIT();
    };

    float oacc[16][4];
    #pragma unroll
    for (int i = 0; i < 16; i++)
        #pragma unroll
        for (int j = 0; j < 4; j++) oacc[i][j] = 0.f;
    float m0 = -INFINITY, m1 = -INFINITY, l0 = 0.f, l1 = 0.f;
    const float scale = 0.08838834764831845f;
    const int row0 = qbase + wid * 16 + (lane >> 2);
    const int row1 = row0 + 8;

    issue_kv(0, 0);

    for (int kt = 0; kt <= ktmax; ++kt) {
        const int buf = kt & 1;
        const int kbase = kt * AK;
        CP_WAIT0();
        __syncthreads();
        if (kt + 1 <= ktmax) issue_kv(kt + 1, buf ^ 1);

        const uint32_t stk = sb + 2 * SQH + buf * STG;
        const uint32_t stv = stk + SKH;

        // ---- S = Q K^T (Q hi/lo fp16 split, K single fp16) ----
        float sacc[16][4];
        #pragma unroll
        for (int i = 0; i < 16; i++)
            #pragma unroll
            for (int j = 0; j < 4; j++) sacc[i][j] = 0.f;
        #pragma unroll
        for (int ks = 0; ks < 8; ks++) {
            uint32_t bk[8][4];
            #pragma unroll
            for (int g = 0; g < 8; g++) {
                uint32_t addr = stk + (g * 16 + b_row) * QR + (ks * 16 + b_kh) * 2;
                ldsm4(bk[g], addr);
            }
            uint32_t qa_h[4], qa_l[4];
            uint32_t addrA = sb + (wid * 16 + a_row) * QR + (ks * 16 + a_kh) * 2;
            ldsm4(qa_h, addrA);
            ldsm4(qa_l, addrA + SQH);
            #pragma unroll
            for (int g = 0; g < 8; g++) {
                #pragma unroll
                for (int h8 = 0; h8 < 2; h8++) {
                    const int nt = g * 2 + h8;
                    mma_f16(sacc[nt], qa_h, bk[g][h8*2], bk[g][h8*2+1]);
                    mma_f16(sacc[nt], qa_l, bk[g][h8*2], bk[g][h8*2+1]);
                }
            }
        }

        // ---- scale + causal mask (diagonal tile only) ----
        const bool need_mask = (kt == ktmax) && (kbase + AK - 1) > (qbase + wid * 16);
        #pragma unroll
        for (int nt = 0; nt < 16; nt++) {
            int c0 = kbase + nt * 8 + (lane & 3) * 2;
            #pragma unroll
            for (int j = 0; j < 4; j++) sacc[nt][j] *= scale;
            if (need_mask) {
                if (c0     > row0) sacc[nt][0] = -INFINITY;
                if (c0 + 1 > row0) sacc[nt][1] = -INFINITY;
                if (c0     > row1) sacc[nt][2] = -INFINITY;
                if (c0 + 1 > row1) sacc[nt][3] = -INFINITY;
            }
        }

        // ---- online softmax ----
        float mx0 = -INFINITY, mx1 = -INFINITY;
        #pragma unroll
        for (int nt = 0; nt < 16; nt++) {
            mx0 = fmaxf(mx0, fmaxf(sacc[nt][0], sacc[nt][1]));
            mx1 = fmaxf(mx1, fmaxf(sacc[nt][2], sacc[nt][3]));
        }
        #pragma unroll
        for (int off = 1; off <= 2; off <<= 1) {
            mx0 = fmaxf(mx0, __shfl_xor_sync(0xffffffffu, mx0, off));
            mx1 = fmaxf(mx1, __shfl_xor_sync(0xffffffffu, mx1, off));
        }
        float nm0 = fmaxf(m0, mx0), nm1 = fmaxf(m1, mx1);
        float sum0 = 0.f, sum1 = 0.f;
        #pragma unroll
        for (int nt = 0; nt < 16; nt++) {
            sacc[nt][0] = __expf(sacc[nt][0] - nm0);
            sacc[nt][1] = __expf(sacc[nt][1] - nm0);
            sacc[nt][2] = __expf(sacc[nt][2] - nm1);
            sacc[nt][3] = __expf(sacc[nt][3] - nm1);
            sum0 += sacc[nt][0] + sacc[nt][1];
            sum1 += sacc[nt][2] + sacc[nt][3];
        }
        #pragma unroll
        for (int off = 1; off <= 2; off <<= 1) {
            sum0 += __shfl_xor_sync(0xffffffffu, sum0, off);
            sum1 += __shfl_xor_sync(0xffffffffu, sum1, off);
        }
        float al0 = __expf(m0 - nm0), al1 = __expf(m1 - nm1);
        l0 = l0 * al0 + sum0; l1 = l1 * al1 + sum1;
        m0 = nm0; m1 = nm1;
        #pragma unroll
        for (int nt = 0; nt < 16; nt++) {
            oacc[nt][0] *= al0; oacc[nt][1] *= al0;
            oacc[nt][2] *= al1; oacc[nt][3] *= al1;
        }

        // ---- O += P V^T (P single fp16) ----
        #pragma unroll
        for (int ks2 = 0; ks2 < 8; ks2++) {
            float* e = sacc[2 * ks2];
            float* o = sacc[2 * ks2 + 1];
            uint32_t pa[4];
            pa[0] = pack_h2(e[0], e[1]);
            pa[1] = pack_h2(e[2], e[3]);
            pa[2] = pack_h2(o[0], o[1]);
            pa[3] = pack_h2(o[2], o[3]);
            #pragma unroll
            for (int g = 0; g < 8; g++) {
                uint32_t vh[4];
                uint32_t addr = stv + (g * 16 + b_row) * QR + (ks2 * 16 + b_kh) * 2;
                ldsm4(vh, addr);
                #pragma unroll
                for (int h8 = 0; h8 < 2; h8++) {
                    const int nt = g * 2 + h8;
                    mma_f16(oacc[nt], pa, vh[h8*2], vh[h8*2+1]);
                }
            }
        }
    }

    // ---- epilogue: O/l -> fp16 hi/lo A-buffers for the Wo GEMM ----
    const float il0 = 1.f / l0, il1 = 1.f / l1;
    #pragma unroll
    for (int nt = 0; nt < 16; nt++) {
        int d = nt * 8 + (lane & 3) * 2;
        size_t i0 = ((size_t)b * SS + row0) * H_DIM + h * HD + d;
        size_t i1 = ((size_t)b * SS + row1) * H_DIM + h * HD + d;
        float v0 = oacc[nt][0] * il0, v1 = oacc[nt][1] * il0;
        float v2 = oacc[nt][2] * il1, v3 = oacc[nt][3] * il1;
        float h0 = h_hi(v0), h1v = h_hi(v1), h2 = h_hi(v2), h3 = h_hi(v3);
        *(uint32_t*)&Oh_g[i0] = pack_h2(h0, h1v);
        *(uint32_t*)&Ol_g[i0] = pack_h2(v0 - h0, v1 - h1v);
        *(uint32_t*)&Oh_g[i1] = pack_h2(h2, h3);
        *(uint32_t*)&Ol_g[i1] = pack_h2(v2 - h2, v3 - h3);
    }
}

// ---------------- launcher ----------------
extern "C" void kernel_launch(void* const* d_in, const int* in_sizes, int n_in,
                              void* d_out, int out_size)
{
    const float* hidden = (const float*)d_in[0];
    const float* Wqkv = (const float*)d_in[2];
    const float* bqkv = (const float*)d_in[3];
    const float* Wo   = (const float*)d_in[4];
    float* out = (float*)d_out;

    float2 *ropetab;
    __half *w1, *w2, *ah, *al, *q_h, *q_l, *k1, *vt;
    cudaGetSymbolAddress((void**)&ropetab, g_rope);
    cudaGetSymbolAddress((void**)&w1, g_W1);
    cudaGetSymbolAddress((void**)&w2, g_W2);
    cudaGetSymbolAddress((void**)&ah, g_A_h);
    cudaGetSymbolAddress((void**)&al, g_A_l);
    cudaGetSymbolAddress((void**)&q_h, g_Qh);
    cudaGetSymbolAddress((void**)&q_l, g_Ql);
    cudaGetSymbolAddress((void**)&k1, g_K1);
    cudaGetSymbolAddress((void**)&vt, g_Vt);

    // prep
    {
        dim3 g1(QKV_DIM / 32, H_DIM / 32);
        transpose_f16_kernel<<<g1, 256>>>(Wqkv, w1, H_DIM, QKV_DIM);
        dim3 g2(H_DIM / 32, H_DIM / 32);
        transpose_f16_kernel<<<g2, 256>>>(Wo, w2, H_DIM, H_DIM);
        int nt = SS * (ROT/2);
        rope_table_kernel<<<(nt + 255) / 256, 256>>>(ropetab);
        int n4 = TOK * H_DIM / 4;
        split_f16_kernel<<<(n4 + 255) / 256, 256>>>((const float4*)hidden,
                                                    (__half2*)ah, (__half2*)al, n4);
    }
    // QKV GEMM fused with bias + RoPE + split scatter
    {
        cudaFuncSetAttribute(gemm_f16_kernel<1>,
                             cudaFuncAttributeMaxDynamicSharedMemorySize, GSMEM);
        dim3 grid(QKV_DIM / BNg, TOK / BMg);
        gemm_f16_kernel<1><<<grid, 512, GSMEM>>>(ah, al, w1, bqkv, nullptr,
                                                 TOK, QKV_DIM, H_DIM, ropetab,
                                                 q_h, q_l, k1, vt);
    }
    // HMMA flash attention
    {
        cudaFuncSetAttribute(attn_kernel,
                             cudaFuncAttributeMaxDynamicSharedMemorySize, ASMEM);
        dim3 grid(SS / AQ, NH, BB);
        attn_kernel<<<grid, 256, ASMEM>>>(q_h, q_l, k1, vt, ah, al);
    }
    // output GEMM
    {
        cudaFuncSetAttribute(gemm_f16_kernel<0>,
                             cudaFuncAttributeMaxDynamicSharedMemorySize, GSMEM);
        dim3 grid(H_DIM / BNg, TOK / BMg);
        gemm_f16_kernel<0><<<grid, 512, GSMEM>>>(ah, al, w2, nullptr, out,
                                                 TOK, H_DIM, H_DIM, nullptr,
                                                 nullptr, nullptr, nullptr, nullptr);
    }
}

// round 15
// speedup vs baseline: 1.9183x; 1.9183x over previous
#include <cuda_runtime.h>
#include <cuda_bf16.h>
#include <cuda_fp16.h>
#include <math.h>
#include <stdint.h>

// ---------------- problem constants ----------------
#define H_DIM 4096
#define NH 32
#define NKV 2
#define HD 128
#define ROT 64
#define BB 2
#define SS 2048
#define QKV_DIM ((NH + 2*NKV)*HD)   // 4608
#define TOK (BB*SS)                 // 4096

// scratch (allocation-free rule: device globals)
__device__ __half g_W1[(size_t)QKV_DIM * H_DIM];     // Wqkv^T fp16 [N][K]
__device__ __half g_W2[(size_t)H_DIM * H_DIM];       // Wo^T fp16 [N][K]
__device__ __half g_A_h[(size_t)TOK * H_DIM];
__device__ __half g_A_l[(size_t)TOK * H_DIM];
__device__ __half g_Qh[(size_t)TOK * NH * HD];
__device__ __half g_Ql[(size_t)TOK * NH * HD];
__device__ __half g_K1[(size_t)TOK * NKV * HD];
__device__ __half g_Vt[(size_t)TOK * NKV * HD];
__device__ float2 g_rope[SS * (ROT/2)];

// ---------------- PTX helpers ----------------
__device__ __forceinline__ uint32_t smem_u32(const void* p) {
    uint32_t a;
    asm("{ .reg .u64 t; cvta.to.shared.u64 t, %1; cvt.u32.u64 %0, t; }"
        : "=r"(a) : "l"(p));
    return a;
}
__device__ __forceinline__ void ldsm4(uint32_t* r, uint32_t addr) {
    asm volatile("ldmatrix.sync.aligned.m8n8.x4.shared.b16 {%0,%1,%2,%3}, [%4];"
                 : "=r"(r[0]), "=r"(r[1]), "=r"(r[2]), "=r"(r[3]) : "r"(addr));
}
__device__ __forceinline__ void mma_f16(float* d, const uint32_t* a,
                                        uint32_t b0, uint32_t b1) {
    asm volatile("mma.sync.aligned.m16n8k16.row.col.f32.f16.f16.f32 "
                 "{%0,%1,%2,%3}, {%4,%5,%6,%7}, {%8,%9}, {%0,%1,%2,%3};"
                 : "+f"(d[0]), "+f"(d[1]), "+f"(d[2]), "+f"(d[3])
                 : "r"(a[0]), "r"(a[1]), "r"(a[2]), "r"(a[3]), "r"(b0), "r"(b1));
}
__device__ __forceinline__ uint32_t pack_h2(float lo, float hi) {
    __half2 t = __floats2half2_rn(lo, hi);
    return *(uint32_t*)&t;
}
__device__ __forceinline__ float h_hi(float x) {
    return __half2float(__float2half_rn(x));
}
#define CP_ASYNC16(dst, src) \
    asm volatile("cp.async.cg.shared.global [%0], [%1], 16;" :: "r"(dst), "l"(src))
#define CP_COMMIT() asm volatile("cp.async.commit_group;" ::: "memory")
#define CP_WAIT1() asm volatile("cp.async.wait_group 1;" ::: "memory")
#define CP_WAIT0() asm volatile("cp.async.wait_group 0;" ::: "memory")

// ---------------- conversion kernels ----------------
__global__ void split_f16_kernel(const float4* __restrict__ x,
                                 __half2* __restrict__ h,
                                 __half2* __restrict__ l, int n4)
{
    int i = blockIdx.x * blockDim.x + threadIdx.x;
    if (i >= n4) return;
    float4 v = x[i];
    float h0 = h_hi(v.x), h1 = h_hi(v.y), h2 = h_hi(v.z), h3 = h_hi(v.w);
    h[2*i]   = __floats2half2_rn(h0, h1);
    h[2*i+1] = __floats2half2_rn(h2, h3);
    l[2*i]   = __floats2half2_rn(v.x - h0, v.y - h1);
    l[2*i+1] = __floats2half2_rn(v.z - h2, v.w - h3);
}

__global__ void transpose_f16_kernel(const float* __restrict__ W,
                                     __half* __restrict__ T, int K, int N)
{
    __shared__ float t[32][33];
    int n0 = blockIdx.x * 32, k0 = blockIdx.y * 32;
    int tx = threadIdx.x & 31, g = threadIdx.x >> 5;
    #pragma unroll
    for (int j = 0; j < 4; j++) {
        int ky = g * 4 + j;
        t[ky][tx] = W[(size_t)(k0 + ky) * N + n0 + tx];
    }
    __syncthreads();
    #pragma unroll
    for (int j = 0; j < 4; j++) {
        int ny = g * 4 + j;
        T[(size_t)(n0 + ny) * K + k0 + tx] = __float2half_rn(t[tx][ny]);
    }
}

__global__ void rope_table_kernel(float2* __restrict__ tab)
{
    int idx = blockIdx.x * blockDim.x + threadIdx.x;
    if (idx >= SS * (ROT/2)) return;
    int s = idx >> 5, i = idx & 31;
    float inv  = 1.0f / powf(10000.0f, (float)(2 * i) / (float)ROT);
    float freq = (float)s * inv;
    double fd = (double)freq;
    tab[idx] = make_float2((float)cos(fd), (float)sin(fd));
}

// ---------------- fp16 HMMA GEMM (3-stage, 1 sync/chunk) ---------------------
// MODE 0: plain fp32 output. MODE 1: QKV epilogue (bias+RoPE+scatter fp16).
// NTERM: number of A split terms (2 = hi+lo, 1 = hi only).
#define BMg 128
#define BNg 128
#define BKg 32
#define ROWB 80
#define TSZ (128*ROWB)     // 10240
#define STGSZ (3*TSZ)      // 30720 (Ah, Al, W)
#define GSMEM (3*STGSZ)    // 92160 (3 stages)

template<int MODE, int NTERM>
__global__ __launch_bounds__(256, 2) void gemm_f16_kernel(
    const __half* __restrict__ Ah, const __half* __restrict__ Al,
    const __half* __restrict__ Bw,
    const float* __restrict__ bias, float* __restrict__ C,
    int M, int N, int K,
    const float2* __restrict__ tab,
    __half* __restrict__ Qh, __half* __restrict__ Ql,
    __half* __restrict__ Kq, __half* __restrict__ Vt)
{
    extern __shared__ char smem[];
    const uint32_t sb = smem_u32(smem);
    const int tid = threadIdx.x;
    const int wid = tid >> 5;
    const int lane = tid & 31;
    const int m0 = blockIdx.y * BMg;
    const int n0 = blockIdx.x * BNg;
    const int NC = K / BKg;

    const int wm = (wid >> 2) * 64;
    const int wn = (wid & 3) * 32;

    const int a_row = (lane & 7) + ((lane >> 3) & 1) * 8;
    const int a_kh  = (lane >> 4) * 8;
    const int b_row = (lane & 7) + ((lane >> 4) & 1) * 8;
    const int b_kh  = ((lane >> 3) & 1) * 8;

    float acc[4][4][4];
    #pragma unroll
    for (int i = 0; i < 4; i++)
        #pragma unroll
        for (int j = 0; j < 4; j++)
            #pragma unroll
            for (int q = 0; q < 4; q++) acc[i][j][q] = 0.f;

    const int lr_lo = tid >> 2;
    const int lc    = tid & 3;
    auto issue_loads = [&](int c, int buf) {
        const int k0 = c * BKg;
        const uint32_t sbuf = sb + buf * STGSZ;
        #pragma unroll
        for (int i = 0; i < 6; i++) {
            const int tensor = i >> 1;
            if (NTERM == 1 && tensor == 1) continue;   // skip A-lo
            const int r = ((i & 1) << 6) + lr_lo;
            const __half* src;
            if (tensor == 0)      src = Ah + (size_t)(m0 + r) * K + k0 + lc * 8;
            else if (tensor == 1) src = Al + (size_t)(m0 + r) * K + k0 + lc * 8;
            else                  src = Bw + (size_t)(n0 + r) * K + k0 + lc * 8;
            uint32_t dst = sbuf + tensor * TSZ + r * ROWB + lc * 16;
            CP_ASYNC16(dst, src);
        }
        CP_COMMIT();
    };

    auto compute = [&](int buf) {
        const uint32_t sbuf = sb + buf * STGSZ;
        #pragma unroll
        for (int ks = 0; ks < 2; ks++) {
            uint32_t br[2][4];
            #pragma unroll
            for (int g = 0; g < 2; g++) {
                uint32_t addr = sbuf + 2 * TSZ +
                    (wn + g * 16 + b_row) * ROWB + (ks * 16 + b_kh) * 2;
                ldsm4(br[g], addr);
            }
            #pragma unroll
            for (int mt = 0; mt < 4; mt++) {
                uint32_t ah[4], al[4];
                uint32_t addrA = sbuf +
                    (wm + mt * 16 + a_row) * ROWB + (ks * 16 + a_kh) * 2;
                ldsm4(ah, addrA);
                if (NTERM == 2) ldsm4(al, addrA + TSZ);
                #pragma unroll
                for (int g = 0; g < 2; g++) {
                    #pragma unroll
                    for (int h8 = 0; h8 < 2; h8++) {
                        const int nt = g * 2 + h8;
                        mma_f16(acc[mt][nt], ah, br[g][h8*2], br[g][h8*2+1]);
                        if (NTERM == 2)
                            mma_f16(acc[mt][nt], al, br[g][h8*2], br[g][h8*2+1]);
                    }
                }
            }
        }
    };

    // 3-stage pipeline, one barrier per chunk
    issue_loads(0, 0);
    issue_loads(1, 1);
    for (int c = 0; c < NC; ++c) {
        if (c + 1 < NC) CP_WAIT1();
        else            CP_WAIT0();
        __syncthreads();
        if (c + 2 < NC) issue_loads(c + 2, (c + 2) % 3);
        compute(c % 3);
    }

    if (MODE == 0) {
        #pragma unroll
        for (int mt = 0; mt < 4; mt++) {
            const int m = m0 + wm + mt * 16 + (lane >> 2);
            #pragma unroll
            for (int nt = 0; nt < 4; nt++) {
                const int n = n0 + wn + nt * 8 + (lane & 3) * 2;
                float b0 = 0.f, b1 = 0.f;
                if (bias) { b0 = bias[n]; b1 = bias[n + 1]; }
                float2 v0, v1;
                v0.x = acc[mt][nt][0] + b0; v0.y = acc[mt][nt][1] + b1;
                v1.x = acc[mt][nt][2] + b0; v1.y = acc[mt][nt][3] + b1;
                *(float2*)&C[(size_t)m * N + n] = v0;
                *(float2*)&C[(size_t)(m + 8) * N + n] = v1;
            }
        }
    } else {
        const int slot = n0 >> 7;
        const int kvv = slot - NH;
        const int kvslot = slot - NH - NKV;
        #pragma unroll
        for (int mt = 0; mt < 4; mt++) {
            const int mrow = m0 + wm + mt * 16 + (lane >> 2);
            const int s0 = mrow & (SS - 1), bb0 = mrow >> 11;
            const int s1 = (mrow + 8) & (SS - 1), bb1 = (mrow + 8) >> 11;
            #pragma unroll
            for (int nt = 0; nt < 4; nt++) {
                const int n = n0 + wn + nt * 8 + (lane & 3) * 2;
                const int d = n & 127;
                float v0 = acc[mt][nt][0] + bias[n];
                float v1 = acc[mt][nt][1] + bias[n + 1];
                float v2 = acc[mt][nt][2] + bias[n];
                float v3 = acc[mt][nt][3] + bias[n + 1];
                if (slot < NH + NKV && d < ROT) {
                    float2 c0 = tab[s0 * (ROT/2) + (d >> 1)];
                    float o0 = v0 * c0.x - v1 * c0.y;
                    float o1 = v1 * c0.x + v0 * c0.y;
                    v0 = o0; v1 = o1;
                    float2 c1 = tab[s1 * (ROT/2) + (d >> 1)];
                    float o2 = v2 * c1.x - v3 * c1.y;
                    float o3 = v3 * c1.x + v2 * c1.y;
                    v2 = o2; v3 = o3;
                }
                if (slot < NH) {
                    float h0 = h_hi(v0), h1 = h_hi(v1);
                    float h2 = h_hi(v2), h3 = h_hi(v3);
                    size_t base0 = ((size_t)(bb0 * NH + slot) * SS + s0) * HD + d;
                    size_t base1 = ((size_t)(bb1 * NH + slot) * SS + s1) * HD + d;
                    *(uint32_t*)&Qh[base0] = pack_h2(h0, h1);
                    *(uint32_t*)&Ql[base0] = pack_h2(v0 - h0, v1 - h1);
                    *(uint32_t*)&Qh[base1] = pack_h2(h2, h3);
                    *(uint32_t*)&Ql[base1] = pack_h2(v2 - h2, v3 - h3);
                } else if (slot < NH + NKV) {
                    size_t base0 = ((size_t)(bb0 * NKV + kvv) * SS + s0) * HD + d;
                    size_t base1 = ((size_t)(bb1 * NKV + kvv) * SS + s1) * HD + d;
                    *(uint32_t*)&Kq[base0] = pack_h2(v0, v1);
                    *(uint32_t*)&Kq[base1] = pack_h2(v2, v3);
                } else {
                    size_t vb0 = ((size_t)(bb0 * NKV + kvslot) * HD + d) * SS + s0;
                    size_t vb1 = ((size_t)(bb1 * NKV + kvslot) * HD + d) * SS + s1;
                    Vt[vb0]      = __float2half_rn(v0);
                    Vt[vb0 + SS] = __float2half_rn(v1);
                    Vt[vb1]      = __float2half_rn(v2);
                    Vt[vb1 + SS] = __float2half_rn(v3);
                }
            }
        }
    }
}

// ---------------- HMMA flash attention (fp16; 2-term S, 1-term PV) -----------
#define AQ 128
#define AK 64
#define QR 272
#define VR 144
#define SQH (AQ*QR)            // 34816
#define SKH (AK*QR)            // 17408
#define SVH (HD*VR)            // 18432
#define STG (SKH + SVH)        // 35840
#define ASMEM (2*SQH + 3*STG)  // 177152

__global__ __launch_bounds__(256, 1) void attn_kernel(
    const __half* __restrict__ Qh_g, const __half* __restrict__ Ql_g,
    const __half* __restrict__ K_g, const __half* __restrict__ Vt_g,
    __half* __restrict__ Oh_g)
{
    extern __shared__ char smem[];
    const uint32_t sb = smem_u32(smem);
    const int tid = threadIdx.x;
    const int wid = tid >> 5;
    const int lane = tid & 31;
    const int qt = gridDim.x - 1 - blockIdx.x;   // LPT: long CTAs first
    const int h  = blockIdx.y;
    const int b  = blockIdx.z;
    const int kvh = h / (NH / NKV);
    const int qbase = qt * AQ;
    const int ktmax = 2 * qt + 1;

    const size_t qoff = ((size_t)(b * NH + h) * SS + qbase) * HD;
    const size_t koff = ((size_t)(b * NKV + kvh) * SS) * HD;
    const size_t voff = ((size_t)(b * NKV + kvh) * HD) * SS;

    const int a_row = (lane & 7) + ((lane >> 3) & 1) * 8;
    const int a_kh  = (lane >> 4) * 8;
    const int b_row = (lane & 7) + ((lane >> 4) & 1) * 8;
    const int b_kh  = ((lane >> 3) & 1) * 8;

    #pragma unroll
    for (int i = 0; i < 8; i++) {
        int flat = i * 256 + tid;
        int r = flat >> 4, u = flat & 15;
        *(uint4*)(smem + r * QR + u * 16) =
            *(const uint4*)(Qh_g + qoff + (size_t)r * HD + u * 8);
        *(uint4*)(smem + SQH + r * QR + u * 16) =
            *(const uint4*)(Ql_g + qoff + (size_t)r * HD + u * 8);
    }

    auto issue_kv = [&](int kt, int buf) {
        const int kbase = kt * AK;
        const uint32_t st = sb + 2 * SQH + buf * STG;
        #pragma unroll
        for (int i = 0; i < 4; i++) {
            int flat = i * 256 + tid;
            int r = flat >> 4, u = flat & 15;
            CP_ASYNC16(st + r * QR + u * 16,
                       K_g + koff + (size_t)(kbase + r) * HD + u * 8);
        }
        #pragma unroll
        for (int i = 0; i < 4; i++) {
            int flat = i * 256 + tid;
            int r = flat >> 3, u = flat & 7;
            CP_ASYNC16(st + SKH + r * VR + u * 16,
                       Vt_g + voff + (size_t)r * SS + kbase + u * 8);
        }
        CP_COMMIT();
    };

    float oacc[16][4];
    #pragma unroll
    for (int i = 0; i < 16; i++)
        #pragma unroll
        for (int j = 0; j < 4; j++) oacc[i][j] = 0.f;
    float m0 = -INFINITY, m1 = -INFINITY, l0 = 0.f, l1 = 0.f;
    const float scale = 0.08838834764831845f;
    const int row0 = qbase + wid * 16 + (lane >> 2);
    const int row1 = row0 + 8;

    issue_kv(0, 0);
    issue_kv(1, 1);

    for (int kt = 0; kt <= ktmax; ++kt) {
        const int buf = kt % 3;
        const int kbase = kt * AK;
        if (kt + 1 <= ktmax) CP_WAIT1();
        else                 CP_WAIT0();
        __syncthreads();
        if (kt + 2 <= ktmax) issue_kv(kt + 2, (kt + 2) % 3);

        const uint32_t stk = sb + 2 * SQH + buf * STG;
        const uint32_t stv = stk + SKH;

        // ---- S = Q K^T (Q 2-term fp16 split, K single fp16) ----
        float sacc[8][4];
        #pragma unroll
        for (int i = 0; i < 8; i++)
            #pragma unroll
            for (int j = 0; j < 4; j++) sacc[i][j] = 0.f;
        #pragma unroll
        for (int ks = 0; ks < 8; ks++) {
            uint32_t bk[4][4];
            #pragma unroll
            for (int g = 0; g < 4; g++) {
                uint32_t addr = stk + (g * 16 + b_row) * QR + (ks * 16 + b_kh) * 2;
                ldsm4(bk[g], addr);
            }
            uint32_t qa_h[4], qa_l[4];
            uint32_t addrA = sb + (wid * 16 + a_row) * QR + (ks * 16 + a_kh) * 2;
            ldsm4(qa_h, addrA);
            ldsm4(qa_l, addrA + SQH);
            #pragma unroll
            for (int g = 0; g < 4; g++) {
                #pragma unroll
                for (int h8 = 0; h8 < 2; h8++) {
                    const int nt = g * 2 + h8;
                    mma_f16(sacc[nt], qa_h, bk[g][h8*2], bk[g][h8*2+1]);
                    mma_f16(sacc[nt], qa_l, bk[g][h8*2], bk[g][h8*2+1]);
                }
            }
        }

        const bool need_mask = (kbase + AK - 1) > (qbase + wid * 16);
        #pragma unroll
        for (int nt = 0; nt < 8; nt++) {
            int c0 = kbase + nt * 8 + (lane & 3) * 2;
            #pragma unroll
            for (int j = 0; j < 4; j++) sacc[nt][j] *= scale;
            if (need_mask) {
                if (c0     > row0) sacc[nt][0] = -INFINITY;
                if (c0 + 1 > row0) sacc[nt][1] = -INFINITY;
                if (c0     > row1) sacc[nt][2] = -INFINITY;
                if (c0 + 1 > row1) sacc[nt][3] = -INFINITY;
            }
        }

        float mx0 = -INFINITY, mx1 = -INFINITY;
        #pragma unroll
        for (int nt = 0; nt < 8; nt++) {
            mx0 = fmaxf(mx0, fmaxf(sacc[nt][0], sacc[nt][1]));
            mx1 = fmaxf(mx1, fmaxf(sacc[nt][2], sacc[nt][3]));
        }
        #pragma unroll
        for (int off = 1; off <= 2; off <<= 1) {
            mx0 = fmaxf(mx0, __shfl_xor_sync(0xffffffffu, mx0, off));
            mx1 = fmaxf(mx1, __shfl_xor_sync(0xffffffffu, mx1, off));
        }
        float nm0 = fmaxf(m0, mx0), nm1 = fmaxf(m1, mx1);
        float sum0 = 0.f, sum1 = 0.f;
        #pragma unroll
        for (int nt = 0; nt < 8; nt++) {
            sacc[nt][0] = __expf(sacc[nt][0] - nm0);
            sacc[nt][1] = __expf(sacc[nt][1] - nm0);
            sacc[nt][2] = __expf(sacc[nt][2] - nm1);
            sacc[nt][3] = __expf(sacc[nt][3] - nm1);
            sum0 += sacc[nt][0] + sacc[nt][1];
            sum1 += sacc[nt][2] + sacc[nt][3];
        }
        #pragma unroll
        for (int off = 1; off <= 2; off <<= 1) {
            sum0 += __shfl_xor_sync(0xffffffffu, sum0, off);
            sum1 += __shfl_xor_sync(0xffffffffu, sum1, off);
        }
        float al0 = __expf(m0 - nm0), al1 = __expf(m1 - nm1);
        l0 = l0 * al0 + sum0; l1 = l1 * al1 + sum1;
        m0 = nm0; m1 = nm1;
        #pragma unroll
        for (int nt = 0; nt < 16; nt++) {
            oacc[nt][0] *= al0; oacc[nt][1] *= al0;
            oacc[nt][2] *= al1; oacc[nt][3] *= al1;
        }

        // ---- O += P V^T (P single fp16) ----
        #pragma unroll
        for (int ks2 = 0; ks2 < 4; ks2++) {
            float* e = sacc[2 * ks2];
            float* o = sacc[2 * ks2 + 1];
            uint32_t pa[4];
            pa[0] = pack_h2(e[0], e[1]);
            pa[1] = pack_h2(e[2], e[3]);
            pa[2] = pack_h2(o[0], o[1]);
            pa[3] = pack_h2(o[2], o[3]);
            #pragma unroll
            for (int g = 0; g < 8; g++) {
                uint32_t vh[4];
                uint32_t addr = stv + (g * 16 + b_row) * VR + (ks2 * 16 + b_kh) * 2;
                ldsm4(vh, addr);
                #pragma unroll
                for (int h8 = 0; h8 < 2; h8++) {
                    const int nt = g * 2 + h8;
                    mma_f16(oacc[nt], pa, vh[h8*2], vh[h8*2+1]);
                }
            }
        }
    }

    // ---- epilogue: O/l -> single fp16 A-buffer for the Wo GEMM ----
    const float il0 = 1.f / l0, il1 = 1.f / l1;
    #pragma unroll
    for (int nt = 0; nt < 16; nt++) {
        int d = nt * 8 + (lane & 3) * 2;
        size_t i0 = ((size_t)b * SS + row0) * H_DIM + h * HD + d;
        size_t i1 = ((size_t)b * SS + row1) * H_DIM + h * HD + d;
        *(uint32_t*)&Oh_g[i0] = pack_h2(oacc[nt][0] * il0, oacc[nt][1] * il0);
        *(uint32_t*)&Oh_g[i1] = pack_h2(oacc[nt][2] * il1, oacc[nt][3] * il1);
    }
}

// ---------------- launcher ----------------
extern "C" void kernel_launch(void* const* d_in, const int* in_sizes, int n_in,
                              void* d_out, int out_size)
{
    const float* hidden = (const float*)d_in[0];
    const float* Wqkv = (const float*)d_in[2];
    const float* bqkv = (const float*)d_in[3];
    const float* Wo   = (const float*)d_in[4];
    float* out = (float*)d_out;

    float2 *ropetab;
    __half *w1, *w2, *ah, *al, *q_h, *q_l, *k1, *vt;
    cudaGetSymbolAddress((void**)&ropetab, g_rope);
    cudaGetSymbolAddress((void**)&w1, g_W1);
    cudaGetSymbolAddress((void**)&w2, g_W2);
    cudaGetSymbolAddress((void**)&ah, g_A_h);
    cudaGetSymbolAddress((void**)&al, g_A_l);
    cudaGetSymbolAddress((void**)&q_h, g_Qh);
    cudaGetSymbolAddress((void**)&q_l, g_Ql);
    cudaGetSymbolAddress((void**)&k1, g_K1);
    cudaGetSymbolAddress((void**)&vt, g_Vt);

    // prep
    {
        dim3 g1(QKV_DIM / 32, H_DIM / 32);
        transpose_f16_kernel<<<g1, 256>>>(Wqkv, w1, H_DIM, QKV_DIM);
        dim3 g2(H_DIM / 32, H_DIM / 32);
        transpose_f16_kernel<<<g2, 256>>>(Wo, w2, H_DIM, H_DIM);
        int nt = SS * (ROT/2);
        rope_table_kernel<<<(nt + 255) / 256, 256>>>(ropetab);
        int n4 = TOK * H_DIM / 4;
        split_f16_kernel<<<(n4 + 255) / 256, 256>>>((const float4*)hidden,
                                                    (__half2*)ah, (__half2*)al, n4);
    }
    // QKV GEMM fused with bias + RoPE + split scatter (2-term A)
    {
        cudaFuncSetAttribute((const void*)gemm_f16_kernel<1, 2>,
                             cudaFuncAttributeMaxDynamicSharedMemorySize, GSMEM);
        dim3 grid(QKV_DIM / BNg, TOK / BMg);
        gemm_f16_kernel<1, 2><<<grid, 256, GSMEM>>>(ah, al, w1, bqkv, nullptr,
                                                    TOK, QKV_DIM, H_DIM, ropetab,
                                                    q_h, q_l, k1, vt);
    }
    // HMMA flash attention (writes single fp16 O into Ah buffer)
    {
        cudaFuncSetAttribute(attn_kernel,
                             cudaFuncAttributeMaxDynamicSharedMemorySize, ASMEM);
        dim3 grid(SS / AQ, NH, BB);
        attn_kernel<<<grid, 256, ASMEM>>>(q_h, q_l, k1, vt, ah);
    }
    // output GEMM (1-term A)
    {
        cudaFuncSetAttribute((const void*)gemm_f16_kernel<0, 1>,
                             cudaFuncAttributeMaxDynamicSharedMemorySize, GSMEM);
        dim3 grid(H_DIM / BNg, TOK / BMg);
        gemm_f16_kernel<0, 1><<<grid, 256, GSMEM>>>(ah, nullptr, w2, nullptr, out,
                                                    TOK, H_DIM, H_DIM, nullptr,
                                                    nullptr, nullptr, nullptr, nullptr);
    }
}

// round 16
// speedup vs baseline: 2.0031x; 1.0442x over previous
#include <cuda_runtime.h>
#include <cuda_bf16.h>
#include <cuda_fp16.h>
#include <math.h>
#include <stdint.h>

// ---------------- problem constants ----------------
#define H_DIM 4096
#define NH 32
#define NKV 2
#define HD 128
#define ROT 64
#define BB 2
#define SS 2048
#define QKV_DIM ((NH + 2*NKV)*HD)   // 4608
#define TOK (BB*SS)                 // 4096

// scratch (allocation-free rule: device globals)
__device__ __half g_W1[(size_t)QKV_DIM * H_DIM];     // Wqkv^T fp16 [N][K]
__device__ __half g_W2[(size_t)H_DIM * H_DIM];       // Wo^T fp16 [N][K]
__device__ __half g_A_h[(size_t)TOK * H_DIM];
__device__ __half g_A_l[(size_t)TOK * H_DIM];
__device__ __half g_Q1[(size_t)TOK * NH * HD];
__device__ __half g_K1[(size_t)TOK * NKV * HD];
__device__ __half g_Vt[(size_t)TOK * NKV * HD];
__device__ float2 g_rope[SS * (ROT/2)];

// ---------------- PTX helpers ----------------
__device__ __forceinline__ uint32_t smem_u32(const void* p) {
    uint32_t a;
    asm("{ .reg .u64 t; cvta.to.shared.u64 t, %1; cvt.u32.u64 %0, t; }"
        : "=r"(a) : "l"(p));
    return a;
}
__device__ __forceinline__ void ldsm4(uint32_t* r, uint32_t addr) {
    asm volatile("ldmatrix.sync.aligned.m8n8.x4.shared.b16 {%0,%1,%2,%3}, [%4];"
                 : "=r"(r[0]), "=r"(r[1]), "=r"(r[2]), "=r"(r[3]) : "r"(addr));
}
__device__ __forceinline__ void mma_f16(float* d, const uint32_t* a,
                                        uint32_t b0, uint32_t b1) {
    asm volatile("mma.sync.aligned.m16n8k16.row.col.f32.f16.f16.f32 "
                 "{%0,%1,%2,%3}, {%4,%5,%6,%7}, {%8,%9}, {%0,%1,%2,%3};"
                 : "+f"(d[0]), "+f"(d[1]), "+f"(d[2]), "+f"(d[3])
                 : "r"(a[0]), "r"(a[1]), "r"(a[2]), "r"(a[3]), "r"(b0), "r"(b1));
}
__device__ __forceinline__ uint32_t pack_h2(float lo, float hi) {
    __half2 t = __floats2half2_rn(lo, hi);
    return *(uint32_t*)&t;
}
__device__ __forceinline__ float h_hi(float x) {
    return __half2float(__float2half_rn(x));
}
#define CP_ASYNC16(dst, src) \
    asm volatile("cp.async.cg.shared.global [%0], [%1], 16;" :: "r"(dst), "l"(src))
#define CP_COMMIT() asm volatile("cp.async.commit_group;" ::: "memory")
#define CP_WAIT1() asm volatile("cp.async.wait_group 1;" ::: "memory")
#define CP_WAIT0() asm volatile("cp.async.wait_group 0;" ::: "memory")

// ---------------- conversion kernels ----------------
__global__ void split_f16_kernel(const float4* __restrict__ x,
                                 __half2* __restrict__ h,
                                 __half2* __restrict__ l, int n4)
{
    int i = blockIdx.x * blockDim.x + threadIdx.x;
    if (i >= n4) return;
    float4 v = x[i];
    float h0 = h_hi(v.x), h1 = h_hi(v.y), h2 = h_hi(v.z), h3 = h_hi(v.w);
    h[2*i]   = __floats2half2_rn(h0, h1);
    h[2*i+1] = __floats2half2_rn(h2, h3);
    l[2*i]   = __floats2half2_rn(v.x - h0, v.y - h1);
    l[2*i+1] = __floats2half2_rn(v.z - h2, v.w - h3);
}

__global__ void transpose_f16_kernel(const float* __restrict__ W,
                                     __half* __restrict__ T, int K, int N)
{
    __shared__ float t[32][33];
    int n0 = blockIdx.x * 32, k0 = blockIdx.y * 32;
    int tx = threadIdx.x & 31, g = threadIdx.x >> 5;
    #pragma unroll
    for (int j = 0; j < 4; j++) {
        int ky = g * 4 + j;
        t[ky][tx] = W[(size_t)(k0 + ky) * N + n0 + tx];
    }
    __syncthreads();
    #pragma unroll
    for (int j = 0; j < 4; j++) {
        int ny = g * 4 + j;
        T[(size_t)(n0 + ny) * K + k0 + tx] = __float2half_rn(t[tx][ny]);
    }
}

__global__ void rope_table_kernel(float2* __restrict__ tab)
{
    int idx = blockIdx.x * blockDim.x + threadIdx.x;
    if (idx >= SS * (ROT/2)) return;
    int s = idx >> 5, i = idx & 31;
    float inv  = 1.0f / powf(10000.0f, (float)(2 * i) / (float)ROT);
    float freq = (float)s * inv;
    double fd = (double)freq;
    tab[idx] = make_float2((float)cos(fd), (float)sin(fd));
}

// ---------------- fp16 HMMA GEMM (3-stage, 1 sync/chunk) ---------------------
// MODE 0: plain fp32 output. MODE 1: QKV epilogue (bias+RoPE+scatter fp16).
// NTERM: number of A split terms (2 = hi+lo, 1 = hi only).
#define BMg 128
#define BNg 128
#define BKg 32
#define ROWB 80
#define TSZ (128*ROWB)     // 10240
#define STGSZ (3*TSZ)      // 30720 (Ah, Al, W)
#define GSMEM (3*STGSZ)    // 92160 (3 stages)

template<int MODE, int NTERM>
__global__ __launch_bounds__(256, 2) void gemm_f16_kernel(
    const __half* __restrict__ Ah, const __half* __restrict__ Al,
    const __half* __restrict__ Bw,
    const float* __restrict__ bias, float* __restrict__ C,
    int M, int N, int K,
    const float2* __restrict__ tab,
    __half* __restrict__ Qq, __half* __restrict__ Kq, __half* __restrict__ Vt)
{
    extern __shared__ char smem[];
    const uint32_t sb = smem_u32(smem);
    const int tid = threadIdx.x;
    const int wid = tid >> 5;
    const int lane = tid & 31;
    const int m0 = blockIdx.y * BMg;
    const int n0 = blockIdx.x * BNg;
    const int NC = K / BKg;

    const int wm = (wid >> 2) * 64;
    const int wn = (wid & 3) * 32;

    const int a_row = (lane & 7) + ((lane >> 3) & 1) * 8;
    const int a_kh  = (lane >> 4) * 8;
    const int b_row = (lane & 7) + ((lane >> 4) & 1) * 8;
    const int b_kh  = ((lane >> 3) & 1) * 8;

    float acc[4][4][4];
    #pragma unroll
    for (int i = 0; i < 4; i++)
        #pragma unroll
        for (int j = 0; j < 4; j++)
            #pragma unroll
            for (int q = 0; q < 4; q++) acc[i][j][q] = 0.f;

    const int lr_lo = tid >> 2;
    const int lc    = tid & 3;
    auto issue_loads = [&](int c, int buf) {
        const int k0 = c * BKg;
        const uint32_t sbuf = sb + buf * STGSZ;
        #pragma unroll
        for (int i = 0; i < 6; i++) {
            const int tensor = i >> 1;
            if (NTERM == 1 && tensor == 1) continue;   // skip A-lo
            const int r = ((i & 1) << 6) + lr_lo;
            const __half* src;
            if (tensor == 0)      src = Ah + (size_t)(m0 + r) * K + k0 + lc * 8;
            else if (tensor == 1) src = Al + (size_t)(m0 + r) * K + k0 + lc * 8;
            else                  src = Bw + (size_t)(n0 + r) * K + k0 + lc * 8;
            uint32_t dst = sbuf + tensor * TSZ + r * ROWB + lc * 16;
            CP_ASYNC16(dst, src);
        }
        CP_COMMIT();
    };

    auto compute = [&](int buf) {
        const uint32_t sbuf = sb + buf * STGSZ;
        #pragma unroll
        for (int ks = 0; ks < 2; ks++) {
            uint32_t br[2][4];
            #pragma unroll
            for (int g = 0; g < 2; g++) {
                uint32_t addr = sbuf + 2 * TSZ +
                    (wn + g * 16 + b_row) * ROWB + (ks * 16 + b_kh) * 2;
                ldsm4(br[g], addr);
            }
            #pragma unroll
            for (int mt = 0; mt < 4; mt++) {
                uint32_t ah[4], al[4];
                uint32_t addrA = sbuf +
                    (wm + mt * 16 + a_row) * ROWB + (ks * 16 + a_kh) * 2;
                ldsm4(ah, addrA);
                if (NTERM == 2) ldsm4(al, addrA + TSZ);
                #pragma unroll
                for (int g = 0; g < 2; g++) {
                    #pragma unroll
                    for (int h8 = 0; h8 < 2; h8++) {
                        const int nt = g * 2 + h8;
                        mma_f16(acc[mt][nt], ah, br[g][h8*2], br[g][h8*2+1]);
                        if (NTERM == 2)
                            mma_f16(acc[mt][nt], al, br[g][h8*2], br[g][h8*2+1]);
                    }
                }
            }
        }
    };

    // 3-stage pipeline, one barrier per chunk
    issue_loads(0, 0);
    issue_loads(1, 1);
    for (int c = 0; c < NC; ++c) {
        if (c + 1 < NC) CP_WAIT1();
        else            CP_WAIT0();
        __syncthreads();
        if (c + 2 < NC) issue_loads(c + 2, (c + 2) % 3);
        compute(c % 3);
    }

    if (MODE == 0) {
        #pragma unroll
        for (int mt = 0; mt < 4; mt++) {
            const int m = m0 + wm + mt * 16 + (lane >> 2);
            #pragma unroll
            for (int nt = 0; nt < 4; nt++) {
                const int n = n0 + wn + nt * 8 + (lane & 3) * 2;
                float b0 = 0.f, b1 = 0.f;
                if (bias) { b0 = bias[n]; b1 = bias[n + 1]; }
                float2 v0, v1;
                v0.x = acc[mt][nt][0] + b0; v0.y = acc[mt][nt][1] + b1;
                v1.x = acc[mt][nt][2] + b0; v1.y = acc[mt][nt][3] + b1;
                *(float2*)&C[(size_t)m * N + n] = v0;
                *(float2*)&C[(size_t)(m + 8) * N + n] = v1;
            }
        }
    } else {
        const int slot = n0 >> 7;
        const int kvv = slot - NH;
        const int kvslot = slot - NH - NKV;
        #pragma unroll
        for (int mt = 0; mt < 4; mt++) {
            const int mrow = m0 + wm + mt * 16 + (lane >> 2);
            const int s0 = mrow & (SS - 1), bb0 = mrow >> 11;
            const int s1 = (mrow + 8) & (SS - 1), bb1 = (mrow + 8) >> 11;
            #pragma unroll
            for (int nt = 0; nt < 4; nt++) {
                const int n = n0 + wn + nt * 8 + (lane & 3) * 2;
                const int d = n & 127;
                float v0 = acc[mt][nt][0] + bias[n];
                float v1 = acc[mt][nt][1] + bias[n + 1];
                float v2 = acc[mt][nt][2] + bias[n];
                float v3 = acc[mt][nt][3] + bias[n + 1];
                if (slot < NH + NKV && d < ROT) {
                    float2 c0 = tab[s0 * (ROT/2) + (d >> 1)];
                    float o0 = v0 * c0.x - v1 * c0.y;
                    float o1 = v1 * c0.x + v0 * c0.y;
                    v0 = o0; v1 = o1;
                    float2 c1 = tab[s1 * (ROT/2) + (d >> 1)];
                    float o2 = v2 * c1.x - v3 * c1.y;
                    float o3 = v3 * c1.x + v2 * c1.y;
                    v2 = o2; v3 = o3;
                }
                if (slot < NH) {
                    size_t base0 = ((size_t)(bb0 * NH + slot) * SS + s0) * HD + d;
                    size_t base1 = ((size_t)(bb1 * NH + slot) * SS + s1) * HD + d;
                    *(uint32_t*)&Qq[base0] = pack_h2(v0, v1);
                    *(uint32_t*)&Qq[base1] = pack_h2(v2, v3);
                } else if (slot < NH + NKV) {
                    size_t base0 = ((size_t)(bb0 * NKV + kvv) * SS + s0) * HD + d;
                    size_t base1 = ((size_t)(bb1 * NKV + kvv) * SS + s1) * HD + d;
                    *(uint32_t*)&Kq[base0] = pack_h2(v0, v1);
                    *(uint32_t*)&Kq[base1] = pack_h2(v2, v3);
                } else {
                    size_t vb0 = ((size_t)(bb0 * NKV + kvslot) * HD + d) * SS + s0;
                    size_t vb1 = ((size_t)(bb1 * NKV + kvslot) * HD + d) * SS + s1;
                    Vt[vb0]      = __float2half_rn(v0);
                    Vt[vb0 + SS] = __float2half_rn(v1);
                    Vt[vb1]      = __float2half_rn(v2);
                    Vt[vb1 + SS] = __float2half_rn(v3);
                }
            }
        }
    }
}

// ---------------- HMMA flash attention (fp16; 1-term S, 1-term PV) -----------
#define AQ 128
#define AK 64
#define QR 272
#define VR 144
#define SQH (AQ*QR)            // 34816 (Q single fp16)
#define SKH (AK*QR)            // 17408
#define SVH (HD*VR)            // 18432
#define STG (SKH + SVH)        // 35840
#define ASMEM (SQH + 3*STG)    // 142336

__global__ __launch_bounds__(256, 1) void attn_kernel(
    const __half* __restrict__ Q_g,
    const __half* __restrict__ K_g, const __half* __restrict__ Vt_g,
    __half* __restrict__ Oh_g)
{
    extern __shared__ char smem[];
    const uint32_t sb = smem_u32(smem);
    const int tid = threadIdx.x;
    const int wid = tid >> 5;
    const int lane = tid & 31;
    const int qt = gridDim.x - 1 - blockIdx.x;   // LPT: long CTAs first
    const int h  = blockIdx.y;
    const int b  = blockIdx.z;
    const int kvh = h / (NH / NKV);
    const int qbase = qt * AQ;
    const int ktmax = 2 * qt + 1;

    const size_t qoff = ((size_t)(b * NH + h) * SS + qbase) * HD;
    const size_t koff = ((size_t)(b * NKV + kvh) * SS) * HD;
    const size_t voff = ((size_t)(b * NKV + kvh) * HD) * SS;

    const int a_row = (lane & 7) + ((lane >> 3) & 1) * 8;
    const int a_kh  = (lane >> 4) * 8;
    const int b_row = (lane & 7) + ((lane >> 4) & 1) * 8;
    const int b_kh  = ((lane >> 3) & 1) * 8;

    #pragma unroll
    for (int i = 0; i < 8; i++) {
        int flat = i * 256 + tid;
        int r = flat >> 4, u = flat & 15;
        *(uint4*)(smem + r * QR + u * 16) =
            *(const uint4*)(Q_g + qoff + (size_t)r * HD + u * 8);
    }

    auto issue_kv = [&](int kt, int buf) {
        const int kbase = kt * AK;
        const uint32_t st = sb + SQH + buf * STG;
        #pragma unroll
        for (int i = 0; i < 4; i++) {
            int flat = i * 256 + tid;
            int r = flat >> 4, u = flat & 15;
            CP_ASYNC16(st + r * QR + u * 16,
                       K_g + koff + (size_t)(kbase + r) * HD + u * 8);
        }
        #pragma unroll
        for (int i = 0; i < 4; i++) {
            int flat = i * 256 + tid;
            int r = flat >> 3, u = flat & 7;
            CP_ASYNC16(st + SKH + r * VR + u * 16,
                       Vt_g + voff + (size_t)r * SS + kbase + u * 8);
        }
        CP_COMMIT();
    };

    float oacc[16][4];
    #pragma unroll
    for (int i = 0; i < 16; i++)
        #pragma unroll
        for (int j = 0; j < 4; j++) oacc[i][j] = 0.f;
    float m0 = -INFINITY, m1 = -INFINITY, l0 = 0.f, l1 = 0.f;
    const float scale = 0.08838834764831845f;
    const int row0 = qbase + wid * 16 + (lane >> 2);
    const int row1 = row0 + 8;

    issue_kv(0, 0);
    issue_kv(1, 1);

    for (int kt = 0; kt <= ktmax; ++kt) {
        const int buf = kt % 3;
        const int kbase = kt * AK;
        if (kt + 1 <= ktmax) CP_WAIT1();
        else                 CP_WAIT0();
        __syncthreads();
        if (kt + 2 <= ktmax) issue_kv(kt + 2, (kt + 2) % 3);

        const uint32_t stk = sb + SQH + buf * STG;
        const uint32_t stv = stk + SKH;

        // ---- S = Q K^T (single fp16 both sides) ----
        float sacc[8][4];
        #pragma unroll
        for (int i = 0; i < 8; i++)
            #pragma unroll
            for (int j = 0; j < 4; j++) sacc[i][j] = 0.f;
        #pragma unroll
        for (int ks = 0; ks < 8; ks++) {
            uint32_t bk[4][4];
            #pragma unroll
            for (int g = 0; g < 4; g++) {
                uint32_t addr = stk + (g * 16 + b_row) * QR + (ks * 16 + b_kh) * 2;
                ldsm4(bk[g], addr);
            }
            uint32_t qa[4];
            uint32_t addrA = sb + (wid * 16 + a_row) * QR + (ks * 16 + a_kh) * 2;
            ldsm4(qa, addrA);
            #pragma unroll
            for (int g = 0; g < 4; g++) {
                #pragma unroll
                for (int h8 = 0; h8 < 2; h8++) {
                    const int nt = g * 2 + h8;
                    mma_f16(sacc[nt], qa, bk[g][h8*2], bk[g][h8*2+1]);
                }
            }
        }

        const bool need_mask = (kbase + AK - 1) > (qbase + wid * 16);
        #pragma unroll
        for (int nt = 0; nt < 8; nt++) {
            int c0 = kbase + nt * 8 + (lane & 3) * 2;
            #pragma unroll
            for (int j = 0; j < 4; j++) sacc[nt][j] *= scale;
            if (need_mask) {
                if (c0     > row0) sacc[nt][0] = -INFINITY;
                if (c0 + 1 > row0) sacc[nt][1] = -INFINITY;
                if (c0     > row1) sacc[nt][2] = -INFINITY;
                if (c0 + 1 > row1) sacc[nt][3] = -INFINITY;
            }
        }

        float mx0 = -INFINITY, mx1 = -INFINITY;
        #pragma unroll
        for (int nt = 0; nt < 8; nt++) {
            mx0 = fmaxf(mx0, fmaxf(sacc[nt][0], sacc[nt][1]));
            mx1 = fmaxf(mx1, fmaxf(sacc[nt][2], sacc[nt][3]));
        }
        #pragma unroll
        for (int off = 1; off <= 2; off <<= 1) {
            mx0 = fmaxf(mx0, __shfl_xor_sync(0xffffffffu, mx0, off));
            mx1 = fmaxf(mx1, __shfl_xor_sync(0xffffffffu, mx1, off));
        }
        float nm0 = fmaxf(m0, mx0), nm1 = fmaxf(m1, mx1);
        float sum0 = 0.f, sum1 = 0.f;
        #pragma unroll
        for (int nt = 0; nt < 8; nt++) {
            sacc[nt][0] = __expf(sacc[nt][0] - nm0);
            sacc[nt][1] = __expf(sacc[nt][1] - nm0);
            sacc[nt][2] = __expf(sacc[nt][2] - nm1);
            sacc[nt][3] = __expf(sacc[nt][3] - nm1);
            sum0 += sacc[nt][0] + sacc[nt][1];
            sum1 += sacc[nt][2] + sacc[nt][3];
        }
        #pragma unroll
        for (int off = 1; off <= 2; off <<= 1) {
            sum0 += __shfl_xor_sync(0xffffffffu, sum0, off);
            sum1 += __shfl_xor_sync(0xffffffffu, sum1, off);
        }
        float al0 = __expf(m0 - nm0), al1 = __expf(m1 - nm1);
        l0 = l0 * al0 + sum0; l1 = l1 * al1 + sum1;
        m0 = nm0; m1 = nm1;
        #pragma unroll
        for (int nt = 0; nt < 16; nt++) {
            oacc[nt][0] *= al0; oacc[nt][1] *= al0;
            oacc[nt][2] *= al1; oacc[nt][3] *= al1;
        }

        // ---- O += P V^T (P single fp16) ----
        #pragma unroll
        for (int ks2 = 0; ks2 < 4; ks2++) {
            float* e = sacc[2 * ks2];
            float* o = sacc[2 * ks2 + 1];
            uint32_t pa[4];
            pa[0] = pack_h2(e[0], e[1]);
            pa[1] = pack_h2(e[2], e[3]);
            pa[2] = pack_h2(o[0], o[1]);
            pa[3] = pack_h2(o[2], o[3]);
            #pragma unroll
            for (int g = 0; g < 8; g++) {
                uint32_t vh[4];
                uint32_t addr = stv + (g * 16 + b_row) * VR + (ks2 * 16 + b_kh) * 2;
                ldsm4(vh, addr);
                #pragma unroll
                for (int h8 = 0; h8 < 2; h8++) {
                    const int nt = g * 2 + h8;
                    mma_f16(oacc[nt], pa, vh[h8*2], vh[h8*2+1]);
                }
            }
        }
    }

    // ---- epilogue: O/l -> single fp16 A-buffer for the Wo GEMM ----
    const float il0 = 1.f / l0, il1 = 1.f / l1;
    #pragma unroll
    for (int nt = 0; nt < 16; nt++) {
        int d = nt * 8 + (lane & 3) * 2;
        size_t i0 = ((size_t)b * SS + row0) * H_DIM + h * HD + d;
        size_t i1 = ((size_t)b * SS + row1) * H_DIM + h * HD + d;
        *(uint32_t*)&Oh_g[i0] = pack_h2(oacc[nt][0] * il0, oacc[nt][1] * il0);
        *(uint32_t*)&Oh_g[i1] = pack_h2(oacc[nt][2] * il1, oacc[nt][3] * il1);
    }
}

// ---------------- launcher ----------------
extern "C" void kernel_launch(void* const* d_in, const int* in_sizes, int n_in,
                              void* d_out, int out_size)
{
    const float* hidden = (const float*)d_in[0];
    const float* Wqkv = (const float*)d_in[2];
    const float* bqkv = (const float*)d_in[3];
    const float* Wo   = (const float*)d_in[4];
    float* out = (float*)d_out;

    float2 *ropetab;
    __half *w1, *w2, *ah, *al, *q1, *k1, *vt;
    cudaGetSymbolAddress((void**)&ropetab, g_rope);
    cudaGetSymbolAddress((void**)&w1, g_W1);
    cudaGetSymbolAddress((void**)&w2, g_W2);
    cudaGetSymbolAddress((void**)&ah, g_A_h);
    cudaGetSymbolAddress((void**)&al, g_A_l);
    cudaGetSymbolAddress((void**)&q1, g_Q1);
    cudaGetSymbolAddress((void**)&k1, g_K1);
    cudaGetSymbolAddress((void**)&vt, g_Vt);

    // prep
    {
        dim3 g1(QKV_DIM / 32, H_DIM / 32);
        transpose_f16_kernel<<<g1, 256>>>(Wqkv, w1, H_DIM, QKV_DIM);
        dim3 g2(H_DIM / 32, H_DIM / 32);
        transpose_f16_kernel<<<g2, 256>>>(Wo, w2, H_DIM, H_DIM);
        int nt = SS * (ROT/2);
        rope_table_kernel<<<(nt + 255) / 256, 256>>>(ropetab);
        int n4 = TOK * H_DIM / 4;
        split_f16_kernel<<<(n4 + 255) / 256, 256>>>((const float4*)hidden,
                                                    (__half2*)ah, (__half2*)al, n4);
    }
    // QKV GEMM fused with bias + RoPE + scatter (2-term A)
    {
        cudaFuncSetAttribute((const void*)gemm_f16_kernel<1, 2>,
                             cudaFuncAttributeMaxDynamicSharedMemorySize, GSMEM);
        dim3 grid(QKV_DIM / BNg, TOK / BMg);
        gemm_f16_kernel<1, 2><<<grid, 256, GSMEM>>>(ah, al, w1, bqkv, nullptr,
                                                    TOK, QKV_DIM, H_DIM, ropetab,
                                                    q1, k1, vt);
    }
    // HMMA flash attention (single-fp16 Q/K/V/P)
    {
        cudaFuncSetAttribute(attn_kernel,
                             cudaFuncAttributeMaxDynamicSharedMemorySize, ASMEM);
        dim3 grid(SS / AQ, NH, BB);
        attn_kernel<<<grid, 256, ASMEM>>>(q1, k1, vt, ah);
    }
    // output GEMM (1-term A)
    {
        cudaFuncSetAttribute((const void*)gemm_f16_kernel<0, 1>,
                             cudaFuncAttributeMaxDynamicSharedMemorySize, GSMEM);
        dim3 grid(H_DIM / BNg, TOK / BMg);
        gemm_f16_kernel<0, 1><<<grid, 256, GSMEM>>>(ah, nullptr, w2, nullptr, out,
                                                    TOK, H_DIM, H_DIM, nullptr,
                                                    nullptr, nullptr, nullptr);
    }
}